// round 15
// baseline (speedup 1.0000x reference)
#include <cuda_runtime.h>
#include <cuda_fp16.h>
#include <cstdint>

#define BS       8
#define CCH      32
#define TLEN     2048
#define PATCH_N  16
#define DM       512
#define NHEADS   8
#define HD       64
#define DFF      2048
#define NLAYERS  3
#define BSEQ     (BS * CCH)       // 256
#define LTOT     240
#define MROWS    (BSEQ * LTOT)    // 61440
#define QKVS     1536

// ---------------- scratch ----------------
__device__ float  g_h  [MROWS * DM];
__device__ float  g_o  [MROWS * DM];
__device__ float  g_bqkv[NLAYERS * QKVS];
__device__ __half g_qkvh[(size_t)MROWS * QKVS];    // fused QKV fp16
__device__ __half g_hh [MROWS * DM];               // h in fp16 (GEMM input)
__device__ __half g_th [MROWS * DM];               // attention out fp16
__device__ __half g_fh [(size_t)MROWS * DFF];      // FFN1 out fp16
#define WTOT 9437184
__device__ __half g_wh [WTOT];

// ---------------- helpers ----------------
__device__ __forceinline__ uint32_t smem_u32(const void* p) {
    uint32_t a;
    asm("{ .reg .u64 t; cvta.to.shared.u64 t, %1; cvt.u32.u64 %0, t; }"
        : "=r"(a) : "l"(p));
    return a;
}
__device__ __forceinline__ void cpasync16(uint32_t d, const void* s) {
    asm volatile("cp.async.cg.shared.global [%0], [%1], 16;"
                 :: "r"(d), "l"(s) : "memory");
}
__device__ __forceinline__ float gelu_tanh(float x) {
    float x3 = x * x * x;
    float t = tanhf(0.7978845608028654f * (x + 0.044715f * x3));
    return 0.5f * x * (1.0f + t);
}
__device__ __forceinline__ uint32_t pack2h(float x, float y) {
    __half2 h = __floats2half2_rn(x, y);
    return *reinterpret_cast<uint32_t*>(&h);
}

#define LDSM_X4(r0, r1, r2, r3, addr) \
    asm volatile("ldmatrix.sync.aligned.m8n8.x4.shared.b16 {%0,%1,%2,%3}, [%4];" \
                 : "=r"(r0), "=r"(r1), "=r"(r2), "=r"(r3) : "r"(addr))

#define LDSM_X4_T(r0, r1, r2, r3, addr) \
    asm volatile("ldmatrix.sync.aligned.m8n8.x4.trans.shared.b16 {%0,%1,%2,%3}, [%4];" \
                 : "=r"(r0), "=r"(r1), "=r"(r2), "=r"(r3) : "r"(addr))

#define MMA_F16(d, a, b0v, b1v) \
    asm volatile("mma.sync.aligned.m16n8k16.row.col.f32.f16.f16.f32 " \
                 "{%0,%1,%2,%3}, {%4,%5,%6,%7}, {%8,%9}, {%0,%1,%2,%3};" \
                 : "+f"((d)[0]), "+f"((d)[1]), "+f"((d)[2]), "+f"((d)[3]) \
                 : "r"((a)[0]), "r"((a)[1]), "r"((a)[2]), "r"((a)[3]), \
                   "r"(b0v), "r"(b1v))

// ---------------- weight conversion ----------------
__global__ void wconv_kernel(const float* __restrict__ w, __half* __restrict__ o, int n4)
{
    int i = blockIdx.x * 256 + threadIdx.x;
    if (i >= n4) return;
    float4 v = ((const float4*)w)[i];
    ((uint2*)o)[i] = make_uint2(pack2h(v.x, v.y), pack2h(v.z, v.w));
}

__global__ void wconv_qkv(const float* __restrict__ Wq, const float* __restrict__ Wk,
                          const float* __restrict__ Wv, __half* __restrict__ o)
{
    int i = blockIdx.x * 256 + threadIdx.x;
    if (i >= NLAYERS * 512 * (QKVS / 4)) return;
    int c4 = i % (QKVS / 4);
    int rem = i / (QKVS / 4);
    int k = rem % 512, L = rem / 512;
    int c = c4 * 4;
    const float* src;
    if (c < 512)        src = Wq + ((size_t)L * 512 + k) * 512 + c;
    else if (c < 1024)  src = Wk + ((size_t)L * 512 + k) * 512 + (c - 512);
    else                src = Wv + ((size_t)L * 512 + k) * 512 + (c - 1024);
    float4 v = *(const float4*)src;
    ((uint2*)o)[i] = make_uint2(pack2h(v.x, v.y), pack2h(v.z, v.w));
}

__global__ void packbias_kernel(const float* __restrict__ bq, const float* __restrict__ bk,
                                const float* __restrict__ bv, float* __restrict__ out)
{
    int i = blockIdx.x * 256 + threadIdx.x;
    if (i >= NLAYERS * QKVS) return;
    int L = i / QKVS, c = i % QKVS;
    float v = (c < 512) ? bq[L * 512 + c]
            : (c < 1024) ? bk[L * 512 + c - 512]
                         : bv[L * 512 + c - 1024];
    out[i] = v;
}

// ---------------- embedding ----------------
__global__ void embed_kernel(const float* __restrict__ x_enc,
                             const float* __restrict__ Wemb,
                             float* __restrict__ h, __half* __restrict__ hh)
{
    int tok = blockIdx.x;
    int r   = blockIdx.y;
    int tid = threadIdx.x;
    int b  = r >> 5;
    int cc = r & 31;

    int kstr, j;
    if (tok < 16)       { kstr = 8; j = tok; }
    else if (tok < 48)  { kstr = 4; j = tok - 16; }
    else if (tok < 112) { kstr = 2; j = tok - 48; }
    else                { kstr = 1; j = tok - 112; }

    __shared__ float xv[PATCH_N];
    if (tid < PATCH_N) {
        int tt = kstr * (j * PATCH_N + tid);
        xv[tid] = x_enc[((size_t)b * TLEN + tt) * CCH + cc];
    }
    __syncthreads();

    float pepos = (float)(j * kstr);
    const float cln = 9.210340371976184f / (float)DM;

    for (int d = tid; d < DM; d += 256) {
        float acc = 0.0f;
        #pragma unroll
        for (int p = 0; p < PATCH_N; p++)
            acc += xv[p] * Wemb[p * DM + d];
        int i2 = d & ~1;
        float ang = pepos * __expf(-(float)i2 * cln);
        float pv = (d & 1) ? cosf(ang) : sinf(ang);
        float val = acc + pv;
        size_t gi = ((size_t)r * LTOT + tok) * DM + d;
        h[gi] = val;
        hh[gi] = __float2half_rn(val);
    }
}

// ---------------- fp16 mma.sync GEMM, 4 warps 64x64, K-slab 64, 3-stage ----------------
#define AST 72          // A smem row stride (halves): 64 + 8 pad -> 144B
#define BST 136         // B smem row stride (halves): 128 + 8 pad -> 272B
#define ST_A 0
#define ST_B 18432      // 128*72*2
#define STAGEB 35840    // 18432 + 64*136*2
#define NSTG 3
#define GSMEM (NSTG * STAGEB)   // 107520

__global__ __launch_bounds__(128, 2)
void gemm_mma(const __half* __restrict__ A, const __half* __restrict__ Bm,
              const float* __restrict__ bias,
              float* __restrict__ C, __half* __restrict__ Ch,
              int M, int N, int K, int doGelu)
{
    extern __shared__ char dsm[];
    uint32_t dynb = smem_u32(dsm);

    int tid  = threadIdx.x;
    int wid  = tid >> 5;
    int lane = tid & 31;
    int wm = wid & 1;
    int wn = wid >> 1;
    int m0 = blockIdx.y * 128;
    int n0 = blockIdx.x * 128;

    float acc[4][8][4];
    #pragma unroll
    for (int i = 0; i < 4; i++)
        #pragma unroll
        for (int j = 0; j < 8; j++)
            #pragma unroll
            for (int c = 0; c < 4; c++) acc[i][j][c] = 0.0f;

    uint32_t aoffL = ((uint32_t)((wm * 64 + (lane & 15)) * AST + (lane >> 4) * 8)) * 2;
    uint32_t boffL = ((uint32_t)(((lane & 7) + ((lane >> 3) & 1) * 8) * BST
                                 + wn * 64 + (lane >> 4) * 8)) * 2;

    int nslab = K >> 6;   // K-slab 64

    auto issue = [&](int j) {
        uint32_t sb = dynb + (uint32_t)(j % NSTG) * STAGEB;
        int k0 = j * 64;
        // A: 128 rows x 64 halves = 1024 16B-chunks, 8 per thread
        #pragma unroll
        for (int i = 0; i < 8; i++) {
            int chunk = i * 128 + tid;
            int row = chunk >> 3, c8 = (chunk & 7) * 8;
            uint32_t off = (uint32_t)(row * AST + c8) * 2;
            cpasync16(sb + ST_A + off, A + (size_t)(m0 + row) * K + k0 + c8);
        }
        // B: 64 rows x 128 halves = 1024 chunks, 8 per thread
        #pragma unroll
        for (int i = 0; i < 8; i++) {
            int chunk = i * 128 + tid;
            int row = chunk >> 4, c8 = (chunk & 15) * 8;
            uint32_t off = (uint32_t)(row * BST + c8) * 2;
            cpasync16(sb + ST_B + off, Bm + (size_t)(k0 + row) * N + n0 + c8);
        }
        asm volatile("cp.async.commit_group;" ::: "memory");
    };

    issue(0); issue(1);
    for (int j = 0; j < nslab; j++) {
        if (j < nslab - 1)
            asm volatile("cp.async.wait_group 1;" ::: "memory");
        else
            asm volatile("cp.async.wait_group 0;" ::: "memory");
        __syncthreads();

        uint32_t sb = dynb + (uint32_t)(j % NSTG) * STAGEB;
        uint32_t aB = sb + ST_A, bB = sb + ST_B;

        if (j + 2 < nslab) issue(j + 2);

        #pragma unroll
        for (int ks = 0; ks < 4; ks++) {
            uint32_t kbA = (uint32_t)(ks * 16) * 2;
            uint32_t kbB = (uint32_t)(ks * 16 * BST) * 2;

            uint32_t ah[4][4];
            #pragma unroll
            for (int mf = 0; mf < 4; mf++) {
                uint32_t off = aoffL + (uint32_t)(mf * 16 * AST) * 2 + kbA;
                LDSM_X4(ah[mf][0], ah[mf][1], ah[mf][2], ah[mf][3], aB + off);
            }
            uint32_t bh[16];
            #pragma unroll
            for (int nb = 0; nb < 4; nb++) {
                uint32_t off = boffL + (uint32_t)(nb * 16) * 2 + kbB;
                LDSM_X4_T(bh[nb * 4 + 0], bh[nb * 4 + 1], bh[nb * 4 + 2], bh[nb * 4 + 3], bB + off);
            }

            #pragma unroll
            for (int mf = 0; mf < 4; mf++)
                #pragma unroll
                for (int nf = 0; nf < 8; nf++)
                    MMA_F16(acc[mf][nf], ah[mf], bh[nf * 2], bh[nf * 2 + 1]);
        }
    }

    int rbase = m0 + wm * 64 + (lane >> 2);
    int cbase = n0 + wn * 64 + (lane & 3) * 2;
    #pragma unroll
    for (int mf = 0; mf < 4; mf++) {
        #pragma unroll
        for (int nf = 0; nf < 8; nf++) {
            int col = cbase + nf * 8;
            float b0v = bias[col], b1v = bias[col + 1];
            float v0 = acc[mf][nf][0] + b0v;
            float v1 = acc[mf][nf][1] + b1v;
            float v2 = acc[mf][nf][2] + b0v;
            float v3 = acc[mf][nf][3] + b1v;
            if (doGelu) {
                v0 = gelu_tanh(v0); v1 = gelu_tanh(v1);
                v2 = gelu_tanh(v2); v3 = gelu_tanh(v3);
            }
            int r0 = rbase + mf * 16;
            if (C) {
                *(float2*)(C + (size_t)r0 * N + col)       = make_float2(v0, v1);
                *(float2*)(C + (size_t)(r0 + 8) * N + col) = make_float2(v2, v3);
            }
            if (Ch) {
                *(uint32_t*)(Ch + (size_t)r0 * N + col)       = pack2h(v0, v1);
                *(uint32_t*)(Ch + (size_t)(r0 + 8) * N + col) = pack2h(v2, v3);
            }
        }
    }
}

// ---------------- tensor-core attention for len 64 / 128 ----------------
template<int LEN>
__global__ __launch_bounds__(256)
void attn_mma(const __half* __restrict__ qkv, __half* __restrict__ th, int start)
{
    constexpr int QST = 72;
    constexpr int KST = LEN + 8;
    constexpr int SST = LEN + 4;
    constexpr int PST = LEN + 8;

    extern __shared__ char smraw[];
    __half* sQ  = (__half*)smraw;                 // [LEN][QST]  (later V)
    __half* sKt = sQ + LEN * QST;                 // [64][KST]
    float*  sS  = (float*)(sKt + 64 * KST);       // [LEN][SST]
    __half* sP  = (__half*)(sS + LEN * SST);      // [LEN][PST]

    int bid = blockIdx.x;
    int hh = bid & 7;
    int b  = bid >> 3;
    int tid = threadIdx.x;
    int wid = tid >> 5, lane = tid & 31;
    int h64 = hh * HD;
    size_t rowbase = (size_t)b * LTOT + start;

    uint32_t sQb = smem_u32(sQ), sKb = smem_u32(sKt);
    uint32_t sPb = smem_u32(sP);

    for (int e = tid; e < LEN * 16; e += 256) {
        int l = e >> 4, c4 = (e & 15) * 4;
        size_t gi = (rowbase + l) * QKVS + h64 + c4;
        uint2 qv = *(const uint2*)(qkv + gi);
        *(uint2*)(sQ + l * QST + c4) = qv;
        __half kvv[4];
        *(uint2*)kvv = *(const uint2*)(qkv + gi + 512);
        #pragma unroll
        for (int i = 0; i < 4; i++)
            sKt[(c4 + i) * KST + l] = kvv[i];
    }
    __syncthreads();

    constexpr int WMS = LEN / 32;
    constexpr int CPW = LEN / (8 / WMS);
    constexpr int NFS = CPW / 8;
    constexpr int NBS = (CPW >= 16) ? CPW / 16 : 1;
    int wm_s = wid % WMS, wn_s = wid / WMS;

    float accs[2][NFS][4];
    #pragma unroll
    for (int i = 0; i < 2; i++)
        #pragma unroll
        for (int j = 0; j < NFS; j++)
            #pragma unroll
            for (int c = 0; c < 4; c++) accs[i][j][c] = 0.0f;

    uint32_t qoff = ((uint32_t)((wm_s * 32 + (lane & 15)) * QST + (lane >> 4) * 8)) * 2;
    uint32_t koff = ((uint32_t)(((lane & 7) + ((lane >> 3) & 1) * 8) * KST
                                + wn_s * CPW + (lane >> 4) * 8)) * 2;

    #pragma unroll
    for (int ks = 0; ks < 4; ks++) {
        uint32_t aq[2][4];
        #pragma unroll
        for (int mf = 0; mf < 2; mf++) {
            uint32_t off = qoff + (uint32_t)(mf * 16 * QST + ks * 16) * 2;
            LDSM_X4(aq[mf][0], aq[mf][1], aq[mf][2], aq[mf][3], sQb + off);
        }
        uint32_t bk[NFS * 2];
        #pragma unroll
        for (int nb = 0; nb < NBS; nb++) {
            uint32_t off = koff + (uint32_t)(ks * 16 * KST + nb * 16) * 2;
            LDSM_X4_T(bk[nb * 4 + 0], bk[nb * 4 + 1], bk[nb * 4 + 2], bk[nb * 4 + 3], sKb + off);
        }
        #pragma unroll
        for (int mf = 0; mf < 2; mf++)
            #pragma unroll
            for (int nf = 0; nf < NFS; nf++)
                MMA_F16(accs[mf][nf], aq[mf], bk[nf * 2], bk[nf * 2 + 1]);
    }

    {
        int r = wm_s * 32 + (lane >> 2);
        int c0 = wn_s * CPW + (lane & 3) * 2;
        #pragma unroll
        for (int mf = 0; mf < 2; mf++)
            #pragma unroll
            for (int nf = 0; nf < NFS; nf++) {
                int rr = r + mf * 16, cc = c0 + nf * 8;
                *(float2*)&sS[rr * SST + cc] =
                    make_float2(accs[mf][nf][0] * 0.125f, accs[mf][nf][1] * 0.125f);
                *(float2*)&sS[(rr + 8) * SST + cc] =
                    make_float2(accs[mf][nf][2] * 0.125f, accs[mf][nf][3] * 0.125f);
            }
    }
    __syncthreads();

    for (int e = tid; e < LEN * 16; e += 256) {
        int l = e >> 4, c4 = (e & 15) * 4;
        uint2 vv = *(const uint2*)(qkv + (rowbase + l) * QKVS + h64 + c4 + 1024);
        *(uint2*)(sQ + l * QST + c4) = vv;
    }
    for (int r = tid; r < LEN; r += 256) {
        float* row = sS + r * SST;
        float mx = -1e30f;
        for (int m = 0; m < LEN; m++) mx = fmaxf(mx, row[m]);
        float sum = 0.0f;
        for (int m = 0; m < LEN; m++) {
            float ev = expf(row[m] - mx);
            row[m] = ev;
            sum += ev;
        }
        float inv = 1.0f / sum;
        __half* prow = sP + r * PST;
        for (int m = 0; m < LEN; m++)
            prow[m] = __float2half_rn(row[m] * inv);
    }
    __syncthreads();

    constexpr int WMP = LEN / 32;
    constexpr int DPW = 8 * WMP;
    constexpr int NFP = DPW / 8;
    constexpr int NBP = (DPW >= 16) ? DPW / 16 : 1;
    constexpr int KSP = LEN / 16;
    int wm_p = wid % WMP, wn_p = wid / WMP;

    float accp[2][NFP][4];
    #pragma unroll
    for (int i = 0; i < 2; i++)
        #pragma unroll
        for (int j = 0; j < NFP; j++)
            #pragma unroll
            for (int c = 0; c < 4; c++) accp[i][j][c] = 0.0f;

    uint32_t poff = ((uint32_t)((wm_p * 32 + (lane & 15)) * PST + (lane >> 4) * 8)) * 2;
    uint32_t voff = ((uint32_t)(((lane & 7) + ((lane >> 3) & 1) * 8) * QST
                                + wn_p * DPW + (lane >> 4) * 8)) * 2;

    #pragma unroll
    for (int ks = 0; ks < KSP; ks++) {
        uint32_t ap[2][4];
        #pragma unroll
        for (int mf = 0; mf < 2; mf++) {
            uint32_t off = poff + (uint32_t)(mf * 16 * PST + ks * 16) * 2;
            LDSM_X4(ap[mf][0], ap[mf][1], ap[mf][2], ap[mf][3], sPb + off);
        }
        uint32_t bv[NFP * 2];
        #pragma unroll
        for (int nb = 0; nb < NBP; nb++) {
            uint32_t off = voff + (uint32_t)(ks * 16 * QST + nb * 16) * 2;
            LDSM_X4_T(bv[nb * 4 + 0], bv[nb * 4 + 1], bv[nb * 4 + 2], bv[nb * 4 + 3], sQb + off);
        }
        #pragma unroll
        for (int mf = 0; mf < 2; mf++)
            #pragma unroll
            for (int nf = 0; nf < NFP; nf++)
                MMA_F16(accp[mf][nf], ap[mf], bv[nf * 2], bv[nf * 2 + 1]);
    }

    {
        int r = wm_p * 32 + (lane >> 2);
        int c0 = wn_p * DPW + (lane & 3) * 2;
        #pragma unroll
        for (int mf = 0; mf < 2; mf++)
            #pragma unroll
            for (int nf = 0; nf < NFP; nf++) {
                int rr = r + mf * 16, cc = c0 + nf * 8;
                *(uint32_t*)(th + (rowbase + rr) * DM + h64 + cc) =
                    pack2h(accp[mf][nf][0], accp[mf][nf][1]);
                *(uint32_t*)(th + (rowbase + rr + 8) * DM + h64 + cc) =
                    pack2h(accp[mf][nf][2], accp[mf][nf][3]);
            }
    }
}

// ---------------- FFMA attention for len 16 / 32 (fp16 qkv input) ----------------
__global__ void attn_small(const __half* __restrict__ qkv,
                           __half* __restrict__ th,
                           int start, int len)
{
    extern __shared__ float sm[];
    int bid = blockIdx.x;
    int hh = bid & 7;
    int b  = bid >> 3;
    int tid = threadIdx.x;        // 256
    int h64 = hh * HD;
    size_t rowbase = (size_t)b * LTOT + start;
    int lenp = len + 4;

    float* sQ  = sm;
    float* sKt = sm + len * HD;
    float* sS  = sKt + HD * lenp;

    for (int e = tid; e < len * HD; e += 256) {
        int l = e >> 6, kk = e & 63;
        size_t gi = (rowbase + l) * QKVS + h64 + kk;
        sQ[e] = __half2float(qkv[gi]);
        sKt[kk * lenp + l] = __half2float(qkv[gi + 512]);
    }
    __syncthreads();

    int nq4 = len >> 2;
    for (int e = tid; e < len * nq4; e += 256) {
        int l  = e / nq4;
        int m4 = (e - l * nq4) * 4;
        const float* qr = sQ + l * HD;
        float ax = 0.0f, ay = 0.0f, az = 0.0f, aw = 0.0f;
        #pragma unroll 8
        for (int kk = 0; kk < HD; kk++) {
            float qv = qr[kk];
            float4 kv = *(const float4*)&sKt[kk * lenp + m4];
            ax += qv * kv.x; ay += qv * kv.y;
            az += qv * kv.z; aw += qv * kv.w;
        }
        float4 rr; rr.x = ax * 0.125f; rr.y = ay * 0.125f;
        rr.z = az * 0.125f; rr.w = aw * 0.125f;
        *(float4*)&sS[l * lenp + m4] = rr;
    }
    __syncthreads();

    for (int e = tid; e < len * HD; e += 256) {
        int l = e >> 6, kk = e & 63;
        sQ[e] = __half2float(qkv[(rowbase + l) * QKVS + h64 + kk + 1024]);
    }
    if (tid < len) {
        float* row = sS + tid * lenp;
        float mx = -1e30f;
        for (int m = 0; m < len; m++) mx = fmaxf(mx, row[m]);
        float sum = 0.0f;
        for (int m = 0; m < len; m++) {
            float ev = expf(row[m] - mx);
            row[m] = ev;
            sum += ev;
        }
        float inv = 1.0f / sum;
        for (int m = 0; m < len; m++) row[m] *= inv;
    }
    __syncthreads();

    for (int e = tid; e < len * (HD / 4); e += 256) {
        int l  = e >> 4;
        int d4 = (e & 15) * 4;
        const float* srow = sS + l * lenp;
        float ax = 0.0f, ay = 0.0f, az = 0.0f, aw = 0.0f;
        #pragma unroll 8
        for (int m = 0; m < len; m++) {
            float s = srow[m];
            float4 vv = *(const float4*)&sQ[m * HD + d4];
            ax += s * vv.x; ay += s * vv.y;
            az += s * vv.z; aw += s * vv.w;
        }
        size_t go = (rowbase + l) * DM + h64 + d4;
        *(uint2*)(th + go) = make_uint2(pack2h(ax, ay), pack2h(az, aw));
    }
}

// ---------------- residual + LayerNorm (+ optional fp16 output) ----------------
__global__ void ln_kernel(const float* __restrict__ x, const float* __restrict__ res,
                          const float* __restrict__ g, const float* __restrict__ bb,
                          float* __restrict__ out, __half* __restrict__ oh,
                          int hasRes)
{
    int row = blockIdx.x;
    int tid = threadIdx.x;   // 128
    float4 vv = ((const float4*)(x + (size_t)row * DM))[tid];
    if (hasRes) {
        float4 rr = ((const float4*)(res + (size_t)row * DM))[tid];
        vv.x += rr.x; vv.y += rr.y; vv.z += rr.z; vv.w += rr.w;
    }
    float sum = vv.x + vv.y + vv.z + vv.w;
    float sq  = vv.x * vv.x + vv.y * vv.y + vv.z * vv.z + vv.w * vv.w;

    #pragma unroll
    for (int off = 16; off; off >>= 1) {
        sum += __shfl_xor_sync(0xFFFFFFFFu, sum, off);
        sq  += __shfl_xor_sync(0xFFFFFFFFu, sq,  off);
    }
    __shared__ float red[2][4];
    int w = tid >> 5;
    if ((tid & 31) == 0) { red[0][w] = sum; red[1][w] = sq; }
    __syncthreads();
    sum = red[0][0] + red[0][1] + red[0][2] + red[0][3];
    sq  = red[1][0] + red[1][1] + red[1][2] + red[1][3];

    float mean = sum * (1.0f / DM);
    float var  = sq * (1.0f / DM) - mean * mean;
    float rstd = rsqrtf(var + 1e-5f);

    float4 gv = ((const float4*)g)[tid];
    float4 bv = ((const float4*)bb)[tid];
    float4 ov;
    ov.x = (vv.x - mean) * rstd * gv.x + bv.x;
    ov.y = (vv.y - mean) * rstd * gv.y + bv.y;
    ov.z = (vv.z - mean) * rstd * gv.z + bv.z;
    ov.w = (vv.w - mean) * rstd * gv.w + bv.w;
    ((float4*)(out + (size_t)row * DM))[tid] = ov;

    if (oh) {
        ((uint2*)(oh + (size_t)row * DM))[tid] =
            make_uint2(pack2h(ov.x, ov.y), pack2h(ov.z, ov.w));
    }
}

// ---------------- host launcher ----------------
extern "C" void kernel_launch(void* const* d_in, const int* in_sizes, int n_in,
                              void* d_out, int out_size)
{
    (void)in_sizes; (void)n_in; (void)out_size;
    const float* x_enc = (const float*)d_in[0];
    const float* W_emb = (const float*)d_in[1];
    const float* Wq    = (const float*)d_in[2];
    const float* bq    = (const float*)d_in[3];
    const float* Wk    = (const float*)d_in[4];
    const float* bk    = (const float*)d_in[5];
    const float* Wv    = (const float*)d_in[6];
    const float* bv    = (const float*)d_in[7];
    const float* Wo    = (const float*)d_in[8];
    const float* bo    = (const float*)d_in[9];
    const float* ln1_g = (const float*)d_in[10];
    const float* ln1_b = (const float*)d_in[11];
    const float* W1    = (const float*)d_in[12];
    const float* b1    = (const float*)d_in[13];
    const float* W2    = (const float*)d_in[14];
    const float* b2    = (const float*)d_in[15];
    const float* ln2_g = (const float*)d_in[16];
    const float* ln2_b = (const float*)d_in[17];
    const float* lnf_g = (const float*)d_in[18];
    const float* lnf_b = (const float*)d_in[19];

    float *h, *ob, *bqkv;
    __half *qkvh, *hh, *th, *fh, *wh;
    cudaGetSymbolAddress((void**)&h,    g_h);
    cudaGetSymbolAddress((void**)&ob,   g_o);
    cudaGetSymbolAddress((void**)&bqkv, g_bqkv);
    cudaGetSymbolAddress((void**)&qkvh, g_qkvh);
    cudaGetSymbolAddress((void**)&hh,   g_hh);
    cudaGetSymbolAddress((void**)&th,   g_th);
    cudaGetSymbolAddress((void**)&fh,   g_fh);
    cudaGetSymbolAddress((void**)&wh,   g_wh);

    cudaFuncSetAttribute(gemm_mma, cudaFuncAttributeMaxDynamicSharedMemorySize, GSMEM);
    cudaFuncSetAttribute(attn_mma<128>, cudaFuncAttributeMaxDynamicSharedMemorySize, 138240);
    cudaFuncSetAttribute(attn_mma<64>,  cudaFuncAttributeMaxDynamicSharedMemorySize, 45056);

    const size_t WD = (size_t)DM * DM;
    const size_t WF = (size_t)DM * DFF;
    const size_t WQKV = (size_t)NLAYERS * 512 * QKVS;
    const size_t OO = WQKV, O1 = OO + 3 * WD, O2 = O1 + 3 * WF;

    wconv_qkv<<<(int)(WQKV / 4 + 255) / 256, 256>>>(Wq, Wk, Wv, wh);
    packbias_kernel<<<(NLAYERS * QKVS + 255) / 256, 256>>>(bq, bk, bv, bqkv);
    wconv_kernel<<<(int)(3 * WD / 4 + 255) / 256, 256>>>(Wo, wh + OO, (int)(3 * WD / 4));
    wconv_kernel<<<(int)(3 * WF / 4 + 255) / 256, 256>>>(W1, wh + O1, (int)(3 * WF / 4));
    wconv_kernel<<<(int)(3 * WF / 4 + 255) / 256, 256>>>(W2, wh + O2, (int)(3 * WF / 4));

    embed_kernel<<<dim3(LTOT, BSEQ), 256>>>(x_enc, W_emb, h, hh);

    dim3 gQKV(QKVS / 128, MROWS / 128);
    dim3 gD(DM / 128, MROWS / 128);
    dim3 gF(DFF / 128, MROWS / 128);

    for (int i = 0; i < NLAYERS; i++) {
        gemm_mma<<<gQKV, 128, GSMEM>>>(hh, wh + (size_t)i * 512 * QKVS,
                                       bqkv + i * QKVS, nullptr, qkvh,
                                       MROWS, QKVS, DM, 0);

        {
            int len = 16, lenp = len + 4;
            size_t smem = (size_t)(len * HD + HD * lenp + len * lenp) * sizeof(float);
            attn_small<<<BSEQ * NHEADS, 256, smem>>>(qkvh, th, 0, len);
        }
        {
            int len = 32, lenp = len + 4;
            size_t smem = (size_t)(len * HD + HD * lenp + len * lenp) * sizeof(float);
            attn_small<<<BSEQ * NHEADS, 256, smem>>>(qkvh, th, 16, len);
        }
        attn_mma<64><<<BSEQ * NHEADS, 256, 45056>>>(qkvh, th, 48);
        attn_mma<128><<<BSEQ * NHEADS, 256, 138240>>>(qkvh, th, 112);

        gemm_mma<<<gD, 128, GSMEM>>>(th, wh + OO + i * WD,
                                     bo + i * DM, ob, nullptr, MROWS, DM, DM, 0);
        ln_kernel<<<MROWS, 128>>>(h, ob, ln1_g + i * DM, ln1_b + i * DM, h, hh, 1);

        gemm_mma<<<gF, 128, GSMEM>>>(hh, wh + O1 + i * WF,
                                     b1 + i * DFF, nullptr, fh, MROWS, DFF, DM, 1);
        gemm_mma<<<gD, 128, GSMEM>>>(fh, wh + O2 + i * WF,
                                     b2 + i * DM, ob, nullptr, MROWS, DM, DFF, 0);
        ln_kernel<<<MROWS, 128>>>(h, ob, ln2_g + i * DM, ln2_b + i * DM, h, hh, 1);
    }

    ln_kernel<<<MROWS, 128>>>(h, nullptr, lnf_g, lnf_b, (float*)d_out, nullptr, 0);
}

// round 16
// speedup vs baseline: 1.0618x; 1.0618x over previous
#include <cuda_runtime.h>
#include <cuda_fp16.h>
#include <cstdint>

#define BS       8
#define CCH      32
#define TLEN     2048
#define PATCH_N  16
#define DM       512
#define NHEADS   8
#define HD       64
#define DFF      2048
#define NLAYERS  3
#define BSEQ     (BS * CCH)       // 256
#define LTOT     240
#define MROWS    (BSEQ * LTOT)    // 61440
#define QKVS     1536

// ---------------- scratch ----------------
__device__ float  g_h  [MROWS * DM];
__device__ float  g_o  [MROWS * DM];
__device__ float  g_bqkv[NLAYERS * QKVS];
__device__ __half g_qkvh[(size_t)MROWS * QKVS];    // fused QKV fp16
__device__ __half g_hh [MROWS * DM];               // h in fp16 (GEMM input)
__device__ __half g_th [MROWS * DM];               // attention out fp16
__device__ __half g_fh [(size_t)MROWS * DFF];      // FFN1 out fp16
#define WTOT 9437184
__device__ __half g_wh [WTOT];

// ---------------- helpers ----------------
__device__ __forceinline__ uint32_t smem_u32(const void* p) {
    uint32_t a;
    asm("{ .reg .u64 t; cvta.to.shared.u64 t, %1; cvt.u32.u64 %0, t; }"
        : "=r"(a) : "l"(p));
    return a;
}
__device__ __forceinline__ void cpasync16(uint32_t d, const void* s) {
    asm volatile("cp.async.cg.shared.global [%0], [%1], 16;"
                 :: "r"(d), "l"(s) : "memory");
}
__device__ __forceinline__ float gelu_tanh(float x) {
    float x3 = x * x * x;
    float t = tanhf(0.7978845608028654f * (x + 0.044715f * x3));
    return 0.5f * x * (1.0f + t);
}
__device__ __forceinline__ uint32_t pack2h(float x, float y) {
    __half2 h = __floats2half2_rn(x, y);
    return *reinterpret_cast<uint32_t*>(&h);
}

#define LDSM_X4(r0, r1, r2, r3, addr) \
    asm volatile("ldmatrix.sync.aligned.m8n8.x4.shared.b16 {%0,%1,%2,%3}, [%4];" \
                 : "=r"(r0), "=r"(r1), "=r"(r2), "=r"(r3) : "r"(addr))

#define LDSM_X4_T(r0, r1, r2, r3, addr) \
    asm volatile("ldmatrix.sync.aligned.m8n8.x4.trans.shared.b16 {%0,%1,%2,%3}, [%4];" \
                 : "=r"(r0), "=r"(r1), "=r"(r2), "=r"(r3) : "r"(addr))

#define MMA_F16(d, a, b0v, b1v) \
    asm volatile("mma.sync.aligned.m16n8k16.row.col.f32.f16.f16.f32 " \
                 "{%0,%1,%2,%3}, {%4,%5,%6,%7}, {%8,%9}, {%0,%1,%2,%3};" \
                 : "+f"((d)[0]), "+f"((d)[1]), "+f"((d)[2]), "+f"((d)[3]) \
                 : "r"((a)[0]), "r"((a)[1]), "r"((a)[2]), "r"((a)[3]), \
                   "r"(b0v), "r"(b1v))

// ---------------- weight conversion ----------------
__global__ void wconv_kernel(const float* __restrict__ w, __half* __restrict__ o, int n4)
{
    int i = blockIdx.x * 256 + threadIdx.x;
    if (i >= n4) return;
    float4 v = ((const float4*)w)[i];
    ((uint2*)o)[i] = make_uint2(pack2h(v.x, v.y), pack2h(v.z, v.w));
}

__global__ void wconv_qkv(const float* __restrict__ Wq, const float* __restrict__ Wk,
                          const float* __restrict__ Wv, __half* __restrict__ o)
{
    int i = blockIdx.x * 256 + threadIdx.x;
    if (i >= NLAYERS * 512 * (QKVS / 4)) return;
    int c4 = i % (QKVS / 4);
    int rem = i / (QKVS / 4);
    int k = rem % 512, L = rem / 512;
    int c = c4 * 4;
    const float* src;
    if (c < 512)        src = Wq + ((size_t)L * 512 + k) * 512 + c;
    else if (c < 1024)  src = Wk + ((size_t)L * 512 + k) * 512 + (c - 512);
    else                src = Wv + ((size_t)L * 512 + k) * 512 + (c - 1024);
    float4 v = *(const float4*)src;
    ((uint2*)o)[i] = make_uint2(pack2h(v.x, v.y), pack2h(v.z, v.w));
}

__global__ void packbias_kernel(const float* __restrict__ bq, const float* __restrict__ bk,
                                const float* __restrict__ bv, float* __restrict__ out)
{
    int i = blockIdx.x * 256 + threadIdx.x;
    if (i >= NLAYERS * QKVS) return;
    int L = i / QKVS, c = i % QKVS;
    float v = (c < 512) ? bq[L * 512 + c]
            : (c < 1024) ? bk[L * 512 + c - 512]
                         : bv[L * 512 + c - 1024];
    out[i] = v;
}

// ---------------- embedding ----------------
__global__ void embed_kernel(const float* __restrict__ x_enc,
                             const float* __restrict__ Wemb,
                             float* __restrict__ h, __half* __restrict__ hh)
{
    int tok = blockIdx.x;
    int r   = blockIdx.y;
    int tid = threadIdx.x;
    int b  = r >> 5;
    int cc = r & 31;

    int kstr, j;
    if (tok < 16)       { kstr = 8; j = tok; }
    else if (tok < 48)  { kstr = 4; j = tok - 16; }
    else if (tok < 112) { kstr = 2; j = tok - 48; }
    else                { kstr = 1; j = tok - 112; }

    __shared__ float xv[PATCH_N];
    if (tid < PATCH_N) {
        int tt = kstr * (j * PATCH_N + tid);
        xv[tid] = x_enc[((size_t)b * TLEN + tt) * CCH + cc];
    }
    __syncthreads();

    float pepos = (float)(j * kstr);
    const float cln = 9.210340371976184f / (float)DM;

    for (int d = tid; d < DM; d += 256) {
        float acc = 0.0f;
        #pragma unroll
        for (int p = 0; p < PATCH_N; p++)
            acc += xv[p] * Wemb[p * DM + d];
        int i2 = d & ~1;
        float ang = pepos * __expf(-(float)i2 * cln);
        float pv = (d & 1) ? cosf(ang) : sinf(ang);
        float val = acc + pv;
        size_t gi = ((size_t)r * LTOT + tok) * DM + d;
        h[gi] = val;
        hh[gi] = __float2half_rn(val);
    }
}

// ---------------- fp16 mma.sync GEMM, 4 warps 64x64, K-slab 32, 4-stage ----------------
// (R13 config + k-step software pipelining of ldsm vs mma)
#define AST 40
#define BST 136
#define ST_A 0
#define ST_B 10240
#define STAGEB 18944
#define NSTG 4
#define GSMEM (NSTG * STAGEB)

__global__ __launch_bounds__(128, 2)
void gemm_mma(const __half* __restrict__ A, const __half* __restrict__ Bm,
              const float* __restrict__ bias,
              float* __restrict__ C, __half* __restrict__ Ch,
              int M, int N, int K, int doGelu)
{
    extern __shared__ char dsm[];
    uint32_t dynb = smem_u32(dsm);

    int tid  = threadIdx.x;
    int wid  = tid >> 5;
    int lane = tid & 31;
    int wm = wid & 1;
    int wn = wid >> 1;
    int m0 = blockIdx.y * 128;
    int n0 = blockIdx.x * 128;

    float acc[4][8][4];
    #pragma unroll
    for (int i = 0; i < 4; i++)
        #pragma unroll
        for (int j = 0; j < 8; j++)
            #pragma unroll
            for (int c = 0; c < 4; c++) acc[i][j][c] = 0.0f;

    uint32_t aoffL = ((uint32_t)((wm * 64 + (lane & 15)) * AST + (lane >> 4) * 8)) * 2;
    uint32_t boffL = ((uint32_t)(((lane & 7) + ((lane >> 3) & 1) * 8) * BST
                                 + wn * 64 + (lane >> 4) * 8)) * 2;

    int nslab = K >> 5;

    auto issue = [&](int j) {
        uint32_t sb = dynb + (uint32_t)(j % NSTG) * STAGEB;
        int k0 = j * 32;
        #pragma unroll
        for (int i = 0; i < 4; i++) {
            int chunk = i * 128 + tid;
            int row = chunk >> 2, c8 = (chunk & 3) * 8;
            uint32_t off = (uint32_t)(row * AST + c8) * 2;
            cpasync16(sb + ST_A + off, A + (size_t)(m0 + row) * K + k0 + c8);
        }
        #pragma unroll
        for (int i = 0; i < 4; i++) {
            int chunk = i * 128 + tid;
            int row = chunk >> 4, c8 = (chunk & 15) * 8;
            uint32_t off = (uint32_t)(row * BST + c8) * 2;
            cpasync16(sb + ST_B + off, Bm + (size_t)(k0 + row) * N + n0 + c8);
        }
        asm volatile("cp.async.commit_group;" ::: "memory");
    };

    // fragment ldsm for one 16-wide k-step
    auto ldfrags = [&](uint32_t aB, uint32_t bB, int ks,
                       uint32_t (&ah)[4][4], uint32_t (&bh)[16]) {
        uint32_t kbA = (uint32_t)(ks * 16) * 2;
        uint32_t kbB = (uint32_t)(ks * 16 * BST) * 2;
        #pragma unroll
        for (int mf = 0; mf < 4; mf++) {
            uint32_t off = aoffL + (uint32_t)(mf * 16 * AST) * 2 + kbA;
            LDSM_X4(ah[mf][0], ah[mf][1], ah[mf][2], ah[mf][3], aB + off);
        }
        #pragma unroll
        for (int nb = 0; nb < 4; nb++) {
            uint32_t off = boffL + (uint32_t)(nb * 16) * 2 + kbB;
            LDSM_X4_T(bh[nb * 4 + 0], bh[nb * 4 + 1], bh[nb * 4 + 2], bh[nb * 4 + 3], bB + off);
        }
    };

    issue(0); issue(1); issue(2);
    uint32_t ahf[2][4][4], bhf[2][16];

    for (int j = 0; j < nslab; j++) {
        if (j < nslab - 2)
            asm volatile("cp.async.wait_group 2;" ::: "memory");
        else if (j == nslab - 2)
            asm volatile("cp.async.wait_group 1;" ::: "memory");
        else
            asm volatile("cp.async.wait_group 0;" ::: "memory");
        __syncthreads();

        uint32_t sb = dynb + (uint32_t)(j % NSTG) * STAGEB;
        uint32_t aB = sb + ST_A, bB = sb + ST_B;

        if (j + 3 < nslab) issue(j + 3);

        // software-pipelined k-steps: ldsm(ks+1) overlaps mma(ks)
        ldfrags(aB, bB, 0, ahf[0], bhf[0]);
        ldfrags(aB, bB, 1, ahf[1], bhf[1]);

        #pragma unroll
        for (int mf = 0; mf < 4; mf++)
            #pragma unroll
            for (int nf = 0; nf < 8; nf++)
                MMA_F16(acc[mf][nf], ahf[0][mf], bhf[0][nf * 2], bhf[0][nf * 2 + 1]);
        #pragma unroll
        for (int mf = 0; mf < 4; mf++)
            #pragma unroll
            for (int nf = 0; nf < 8; nf++)
                MMA_F16(acc[mf][nf], ahf[1][mf], bhf[1][nf * 2], bhf[1][nf * 2 + 1]);
    }

    int rbase = m0 + wm * 64 + (lane >> 2);
    int cbase = n0 + wn * 64 + (lane & 3) * 2;
    #pragma unroll
    for (int mf = 0; mf < 4; mf++) {
        #pragma unroll
        for (int nf = 0; nf < 8; nf++) {
            int col = cbase + nf * 8;
            float b0v = bias[col], b1v = bias[col + 1];
            float v0 = acc[mf][nf][0] + b0v;
            float v1 = acc[mf][nf][1] + b1v;
            float v2 = acc[mf][nf][2] + b0v;
            float v3 = acc[mf][nf][3] + b1v;
            if (doGelu) {
                v0 = gelu_tanh(v0); v1 = gelu_tanh(v1);
                v2 = gelu_tanh(v2); v3 = gelu_tanh(v3);
            }
            int r0 = rbase + mf * 16;
            if (C) {
                *(float2*)(C + (size_t)r0 * N + col)       = make_float2(v0, v1);
                *(float2*)(C + (size_t)(r0 + 8) * N + col) = make_float2(v2, v3);
            }
            if (Ch) {
                *(uint32_t*)(Ch + (size_t)r0 * N + col)       = pack2h(v0, v1);
                *(uint32_t*)(Ch + (size_t)(r0 + 8) * N + col) = pack2h(v2, v3);
            }
        }
    }
}

// ---------------- tensor-core attention for len 64 / 128 ----------------
template<int LEN>
__global__ __launch_bounds__(256)
void attn_mma(const __half* __restrict__ qkv, __half* __restrict__ th, int start)
{
    constexpr int QST = 72;
    constexpr int KST = LEN + 8;
    constexpr int SST = LEN + 4;
    constexpr int PST = LEN + 8;

    extern __shared__ char smraw[];
    __half* sQ  = (__half*)smraw;                 // [LEN][QST]  (later V)
    __half* sKt = sQ + LEN * QST;                 // [64][KST]
    float*  sS  = (float*)(sKt + 64 * KST);       // [LEN][SST]
    __half* sP  = (__half*)(sS + LEN * SST);      // [LEN][PST]

    int bid = blockIdx.x;
    int hh = bid & 7;
    int b  = bid >> 3;
    int tid = threadIdx.x;
    int wid = tid >> 5, lane = tid & 31;
    int h64 = hh * HD;
    size_t rowbase = (size_t)b * LTOT + start;

    uint32_t sQb = smem_u32(sQ), sKb = smem_u32(sKt);
    uint32_t sPb = smem_u32(sP);

    for (int e = tid; e < LEN * 16; e += 256) {
        int l = e >> 4, c4 = (e & 15) * 4;
        size_t gi = (rowbase + l) * QKVS + h64 + c4;
        uint2 qv = *(const uint2*)(qkv + gi);
        *(uint2*)(sQ + l * QST + c4) = qv;
        __half kvv[4];
        *(uint2*)kvv = *(const uint2*)(qkv + gi + 512);
        #pragma unroll
        for (int i = 0; i < 4; i++)
            sKt[(c4 + i) * KST + l] = kvv[i];
    }
    __syncthreads();

    constexpr int WMS = LEN / 32;
    constexpr int CPW = LEN / (8 / WMS);
    constexpr int NFS = CPW / 8;
    constexpr int NBS = (CPW >= 16) ? CPW / 16 : 1;
    int wm_s = wid % WMS, wn_s = wid / WMS;

    float accs[2][NFS][4];
    #pragma unroll
    for (int i = 0; i < 2; i++)
        #pragma unroll
        for (int j = 0; j < NFS; j++)
            #pragma unroll
            for (int c = 0; c < 4; c++) accs[i][j][c] = 0.0f;

    uint32_t qoff = ((uint32_t)((wm_s * 32 + (lane & 15)) * QST + (lane >> 4) * 8)) * 2;
    uint32_t koff = ((uint32_t)(((lane & 7) + ((lane >> 3) & 1) * 8) * KST
                                + wn_s * CPW + (lane >> 4) * 8)) * 2;

    #pragma unroll
    for (int ks = 0; ks < 4; ks++) {
        uint32_t aq[2][4];
        #pragma unroll
        for (int mf = 0; mf < 2; mf++) {
            uint32_t off = qoff + (uint32_t)(mf * 16 * QST + ks * 16) * 2;
            LDSM_X4(aq[mf][0], aq[mf][1], aq[mf][2], aq[mf][3], sQb + off);
        }
        uint32_t bk[NFS * 2];
        #pragma unroll
        for (int nb = 0; nb < NBS; nb++) {
            uint32_t off = koff + (uint32_t)(ks * 16 * KST + nb * 16) * 2;
            LDSM_X4_T(bk[nb * 4 + 0], bk[nb * 4 + 1], bk[nb * 4 + 2], bk[nb * 4 + 3], sKb + off);
        }
        #pragma unroll
        for (int mf = 0; mf < 2; mf++)
            #pragma unroll
            for (int nf = 0; nf < NFS; nf++)
                MMA_F16(accs[mf][nf], aq[mf], bk[nf * 2], bk[nf * 2 + 1]);
    }

    {
        int r = wm_s * 32 + (lane >> 2);
        int c0 = wn_s * CPW + (lane & 3) * 2;
        #pragma unroll
        for (int mf = 0; mf < 2; mf++)
            #pragma unroll
            for (int nf = 0; nf < NFS; nf++) {
                int rr = r + mf * 16, cc = c0 + nf * 8;
                *(float2*)&sS[rr * SST + cc] =
                    make_float2(accs[mf][nf][0] * 0.125f, accs[mf][nf][1] * 0.125f);
                *(float2*)&sS[(rr + 8) * SST + cc] =
                    make_float2(accs[mf][nf][2] * 0.125f, accs[mf][nf][3] * 0.125f);
            }
    }
    __syncthreads();

    for (int e = tid; e < LEN * 16; e += 256) {
        int l = e >> 4, c4 = (e & 15) * 4;
        uint2 vv = *(const uint2*)(qkv + (rowbase + l) * QKVS + h64 + c4 + 1024);
        *(uint2*)(sQ + l * QST + c4) = vv;
    }
    for (int r = tid; r < LEN; r += 256) {
        float* row = sS + r * SST;
        float mx = -1e30f;
        for (int m = 0; m < LEN; m++) mx = fmaxf(mx, row[m]);
        float sum = 0.0f;
        for (int m = 0; m < LEN; m++) {
            float ev = expf(row[m] - mx);
            row[m] = ev;
            sum += ev;
        }
        float inv = 1.0f / sum;
        __half* prow = sP + r * PST;
        for (int m = 0; m < LEN; m++)
            prow[m] = __float2half_rn(row[m] * inv);
    }
    __syncthreads();

    constexpr int WMP = LEN / 32;
    constexpr int DPW = 8 * WMP;
    constexpr int NFP = DPW / 8;
    constexpr int NBP = (DPW >= 16) ? DPW / 16 : 1;
    constexpr int KSP = LEN / 16;
    int wm_p = wid % WMP, wn_p = wid / WMP;

    float accp[2][NFP][4];
    #pragma unroll
    for (int i = 0; i < 2; i++)
        #pragma unroll
        for (int j = 0; j < NFP; j++)
            #pragma unroll
            for (int c = 0; c < 4; c++) accp[i][j][c] = 0.0f;

    uint32_t poff = ((uint32_t)((wm_p * 32 + (lane & 15)) * PST + (lane >> 4) * 8)) * 2;
    uint32_t voff = ((uint32_t)(((lane & 7) + ((lane >> 3) & 1) * 8) * QST
                                + wn_p * DPW + (lane >> 4) * 8)) * 2;

    #pragma unroll
    for (int ks = 0; ks < KSP; ks++) {
        uint32_t ap[2][4];
        #pragma unroll
        for (int mf = 0; mf < 2; mf++) {
            uint32_t off = poff + (uint32_t)(mf * 16 * PST + ks * 16) * 2;
            LDSM_X4(ap[mf][0], ap[mf][1], ap[mf][2], ap[mf][3], sPb + off);
        }
        uint32_t bv[NFP * 2];
        #pragma unroll
        for (int nb = 0; nb < NBP; nb++) {
            uint32_t off = voff + (uint32_t)(ks * 16 * QST + nb * 16) * 2;
            LDSM_X4_T(bv[nb * 4 + 0], bv[nb * 4 + 1], bv[nb * 4 + 2], bv[nb * 4 + 3], sQb + off);
        }
        #pragma unroll
        for (int mf = 0; mf < 2; mf++)
            #pragma unroll
            for (int nf = 0; nf < NFP; nf++)
                MMA_F16(accp[mf][nf], ap[mf], bv[nf * 2], bv[nf * 2 + 1]);
    }

    {
        int r = wm_p * 32 + (lane >> 2);
        int c0 = wn_p * DPW + (lane & 3) * 2;
        #pragma unroll
        for (int mf = 0; mf < 2; mf++)
            #pragma unroll
            for (int nf = 0; nf < NFP; nf++) {
                int rr = r + mf * 16, cc = c0 + nf * 8;
                *(uint32_t*)(th + (rowbase + rr) * DM + h64 + cc) =
                    pack2h(accp[mf][nf][0], accp[mf][nf][1]);
                *(uint32_t*)(th + (rowbase + rr + 8) * DM + h64 + cc) =
                    pack2h(accp[mf][nf][2], accp[mf][nf][3]);
            }
    }
}

// ---------------- FFMA attention for len 16 / 32 (fp16 qkv input) ----------------
__global__ void attn_small(const __half* __restrict__ qkv,
                           __half* __restrict__ th,
                           int start, int len)
{
    extern __shared__ float sm[];
    int bid = blockIdx.x;
    int hh = bid & 7;
    int b  = bid >> 3;
    int tid = threadIdx.x;        // 256
    int h64 = hh * HD;
    size_t rowbase = (size_t)b * LTOT + start;
    int lenp = len + 4;

    float* sQ  = sm;
    float* sKt = sm + len * HD;
    float* sS  = sKt + HD * lenp;

    for (int e = tid; e < len * HD; e += 256) {
        int l = e >> 6, kk = e & 63;
        size_t gi = (rowbase + l) * QKVS + h64 + kk;
        sQ[e] = __half2float(qkv[gi]);
        sKt[kk * lenp + l] = __half2float(qkv[gi + 512]);
    }
    __syncthreads();

    int nq4 = len >> 2;
    for (int e = tid; e < len * nq4; e += 256) {
        int l  = e / nq4;
        int m4 = (e - l * nq4) * 4;
        const float* qr = sQ + l * HD;
        float ax = 0.0f, ay = 0.0f, az = 0.0f, aw = 0.0f;
        #pragma unroll 8
        for (int kk = 0; kk < HD; kk++) {
            float qv = qr[kk];
            float4 kv = *(const float4*)&sKt[kk * lenp + m4];
            ax += qv * kv.x; ay += qv * kv.y;
            az += qv * kv.z; aw += qv * kv.w;
        }
        float4 rr; rr.x = ax * 0.125f; rr.y = ay * 0.125f;
        rr.z = az * 0.125f; rr.w = aw * 0.125f;
        *(float4*)&sS[l * lenp + m4] = rr;
    }
    __syncthreads();

    for (int e = tid; e < len * HD; e += 256) {
        int l = e >> 6, kk = e & 63;
        sQ[e] = __half2float(qkv[(rowbase + l) * QKVS + h64 + kk + 1024]);
    }
    if (tid < len) {
        float* row = sS + tid * lenp;
        float mx = -1e30f;
        for (int m = 0; m < len; m++) mx = fmaxf(mx, row[m]);
        float sum = 0.0f;
        for (int m = 0; m < len; m++) {
            float ev = expf(row[m] - mx);
            row[m] = ev;
            sum += ev;
        }
        float inv = 1.0f / sum;
        for (int m = 0; m < len; m++) row[m] *= inv;
    }
    __syncthreads();

    for (int e = tid; e < len * (HD / 4); e += 256) {
        int l  = e >> 4;
        int d4 = (e & 15) * 4;
        const float* srow = sS + l * lenp;
        float ax = 0.0f, ay = 0.0f, az = 0.0f, aw = 0.0f;
        #pragma unroll 8
        for (int m = 0; m < len; m++) {
            float s = srow[m];
            float4 vv = *(const float4*)&sQ[m * HD + d4];
            ax += s * vv.x; ay += s * vv.y;
            az += s * vv.z; aw += s * vv.w;
        }
        size_t go = (rowbase + l) * DM + h64 + d4;
        *(uint2*)(th + go) = make_uint2(pack2h(ax, ay), pack2h(az, aw));
    }
}

// ---------------- residual + LayerNorm (+ optional fp16 output) ----------------
__global__ void ln_kernel(const float* __restrict__ x, const float* __restrict__ res,
                          const float* __restrict__ g, const float* __restrict__ bb,
                          float* __restrict__ out, __half* __restrict__ oh,
                          int hasRes)
{
    int row = blockIdx.x;
    int tid = threadIdx.x;   // 128
    float4 vv = ((const float4*)(x + (size_t)row * DM))[tid];
    if (hasRes) {
        float4 rr = ((const float4*)(res + (size_t)row * DM))[tid];
        vv.x += rr.x; vv.y += rr.y; vv.z += rr.z; vv.w += rr.w;
    }
    float sum = vv.x + vv.y + vv.z + vv.w;
    float sq  = vv.x * vv.x + vv.y * vv.y + vv.z * vv.z + vv.w * vv.w;

    #pragma unroll
    for (int off = 16; off; off >>= 1) {
        sum += __shfl_xor_sync(0xFFFFFFFFu, sum, off);
        sq  += __shfl_xor_sync(0xFFFFFFFFu, sq,  off);
    }
    __shared__ float red[2][4];
    int w = tid >> 5;
    if ((tid & 31) == 0) { red[0][w] = sum; red[1][w] = sq; }
    __syncthreads();
    sum = red[0][0] + red[0][1] + red[0][2] + red[0][3];
    sq  = red[1][0] + red[1][1] + red[1][2] + red[1][3];

    float mean = sum * (1.0f / DM);
    float var  = sq * (1.0f / DM) - mean * mean;
    float rstd = rsqrtf(var + 1e-5f);

    float4 gv = ((const float4*)g)[tid];
    float4 bv = ((const float4*)bb)[tid];
    float4 ov;
    ov.x = (vv.x - mean) * rstd * gv.x + bv.x;
    ov.y = (vv.y - mean) * rstd * gv.y + bv.y;
    ov.z = (vv.z - mean) * rstd * gv.z + bv.z;
    ov.w = (vv.w - mean) * rstd * gv.w + bv.w;
    ((float4*)(out + (size_t)row * DM))[tid] = ov;

    if (oh) {
        ((uint2*)(oh + (size_t)row * DM))[tid] =
            make_uint2(pack2h(ov.x, ov.y), pack2h(ov.z, ov.w));
    }
}

// ---------------- host launcher ----------------
extern "C" void kernel_launch(void* const* d_in, const int* in_sizes, int n_in,
                              void* d_out, int out_size)
{
    (void)in_sizes; (void)n_in; (void)out_size;
    const float* x_enc = (const float*)d_in[0];
    const float* W_emb = (const float*)d_in[1];
    const float* Wq    = (const float*)d_in[2];
    const float* bq    = (const float*)d_in[3];
    const float* Wk    = (const float*)d_in[4];
    const float* bk    = (const float*)d_in[5];
    const float* Wv    = (const float*)d_in[6];
    const float* bv    = (const float*)d_in[7];
    const float* Wo    = (const float*)d_in[8];
    const float* bo    = (const float*)d_in[9];
    const float* ln1_g = (const float*)d_in[10];
    const float* ln1_b = (const float*)d_in[11];
    const float* W1    = (const float*)d_in[12];
    const float* b1    = (const float*)d_in[13];
    const float* W2    = (const float*)d_in[14];
    const float* b2    = (const float*)d_in[15];
    const float* ln2_g = (const float*)d_in[16];
    const float* ln2_b = (const float*)d_in[17];
    const float* lnf_g = (const float*)d_in[18];
    const float* lnf_b = (const float*)d_in[19];

    float *h, *ob, *bqkv;
    __half *qkvh, *hh, *th, *fh, *wh;
    cudaGetSymbolAddress((void**)&h,    g_h);
    cudaGetSymbolAddress((void**)&ob,   g_o);
    cudaGetSymbolAddress((void**)&bqkv, g_bqkv);
    cudaGetSymbolAddress((void**)&qkvh, g_qkvh);
    cudaGetSymbolAddress((void**)&hh,   g_hh);
    cudaGetSymbolAddress((void**)&th,   g_th);
    cudaGetSymbolAddress((void**)&fh,   g_fh);
    cudaGetSymbolAddress((void**)&wh,   g_wh);

    cudaFuncSetAttribute(gemm_mma, cudaFuncAttributeMaxDynamicSharedMemorySize, GSMEM);
    cudaFuncSetAttribute(attn_mma<128>, cudaFuncAttributeMaxDynamicSharedMemorySize, 138240);
    cudaFuncSetAttribute(attn_mma<64>,  cudaFuncAttributeMaxDynamicSharedMemorySize, 45056);

    const size_t WD = (size_t)DM * DM;
    const size_t WF = (size_t)DM * DFF;
    const size_t WQKV = (size_t)NLAYERS * 512 * QKVS;
    const size_t OO = WQKV, O1 = OO + 3 * WD, O2 = O1 + 3 * WF;

    wconv_qkv<<<(int)(WQKV / 4 + 255) / 256, 256>>>(Wq, Wk, Wv, wh);
    packbias_kernel<<<(NLAYERS * QKVS + 255) / 256, 256>>>(bq, bk, bv, bqkv);
    wconv_kernel<<<(int)(3 * WD / 4 + 255) / 256, 256>>>(Wo, wh + OO, (int)(3 * WD / 4));
    wconv_kernel<<<(int)(3 * WF / 4 + 255) / 256, 256>>>(W1, wh + O1, (int)(3 * WF / 4));
    wconv_kernel<<<(int)(3 * WF / 4 + 255) / 256, 256>>>(W2, wh + O2, (int)(3 * WF / 4));

    embed_kernel<<<dim3(LTOT, BSEQ), 256>>>(x_enc, W_emb, h, hh);

    dim3 gQKV(QKVS / 128, MROWS / 128);
    dim3 gD(DM / 128, MROWS / 128);
    dim3 gF(DFF / 128, MROWS / 128);

    for (int i = 0; i < NLAYERS; i++) {
        gemm_mma<<<gQKV, 128, GSMEM>>>(hh, wh + (size_t)i * 512 * QKVS,
                                       bqkv + i * QKVS, nullptr, qkvh,
                                       MROWS, QKVS, DM, 0);

        {
            int len = 16, lenp = len + 4;
            size_t smem = (size_t)(len * HD + HD * lenp + len * lenp) * sizeof(float);
            attn_small<<<BSEQ * NHEADS, 256, smem>>>(qkvh, th, 0, len);
        }
        {
            int len = 32, lenp = len + 4;
            size_t smem = (size_t)(len * HD + HD * lenp + len * lenp) * sizeof(float);
            attn_small<<<BSEQ * NHEADS, 256, smem>>>(qkvh, th, 16, len);
        }
        attn_mma<64><<<BSEQ * NHEADS, 256, 45056>>>(qkvh, th, 48);
        attn_mma<128><<<BSEQ * NHEADS, 256, 138240>>>(qkvh, th, 112);

        gemm_mma<<<gD, 128, GSMEM>>>(th, wh + OO + i * WD,
                                     bo + i * DM, ob, nullptr, MROWS, DM, DM, 0);
        ln_kernel<<<MROWS, 128>>>(h, ob, ln1_g + i * DM, ln1_b + i * DM, h, hh, 1);

        gemm_mma<<<gF, 128, GSMEM>>>(hh, wh + O1 + i * WF,
                                     b1 + i * DFF, nullptr, fh, MROWS, DFF, DM, 1);
        gemm_mma<<<gD, 128, GSMEM>>>(fh, wh + O2 + i * WF,
                                     b2 + i * DM, ob, nullptr, MROWS, DM, DFF, 0);
        ln_kernel<<<MROWS, 128>>>(h, ob, ln2_g + i * DM, ln2_b + i * DM, h, hh, 1);
    }

    ln_kernel<<<MROWS, 128>>>(h, nullptr, lnf_g, lnf_b, (float*)d_out, nullptr, 0);
}

// round 17
// speedup vs baseline: 1.0780x; 1.0153x over previous
#include <cuda_runtime.h>
#include <cuda_fp16.h>
#include <cstdint>

#define BS       8
#define CCH      32
#define TLEN     2048
#define PATCH_N  16
#define DM       512
#define NHEADS   8
#define HD       64
#define DFF      2048
#define NLAYERS  3
#define BSEQ     (BS * CCH)       // 256
#define LTOT     240
#define MROWS    (BSEQ * LTOT)    // 61440
#define QKVS     1536

// ---------------- scratch ----------------
__device__ float  g_h  [MROWS * DM];
__device__ float  g_bqkv[NLAYERS * QKVS];
__device__ __half g_oh [MROWS * DM];               // residual branch fp16
__device__ __half g_qkvh[(size_t)MROWS * QKVS];    // fused QKV fp16
__device__ __half g_hh [MROWS * DM];               // h in fp16 (GEMM input)
__device__ __half g_th [MROWS * DM];               // attention out fp16
__device__ __half g_fh [(size_t)MROWS * DFF];      // FFN1 out fp16
#define WTOT 9437184
__device__ __half g_wh [WTOT];

// ---------------- helpers ----------------
__device__ __forceinline__ uint32_t smem_u32(const void* p) {
    uint32_t a;
    asm("{ .reg .u64 t; cvta.to.shared.u64 t, %1; cvt.u32.u64 %0, t; }"
        : "=r"(a) : "l"(p));
    return a;
}
__device__ __forceinline__ void cpasync16(uint32_t d, const void* s) {
    asm volatile("cp.async.cg.shared.global [%0], [%1], 16;"
                 :: "r"(d), "l"(s) : "memory");
}
__device__ __forceinline__ float gelu_tanh(float x) {
    float x3 = x * x * x;
    float t = tanhf(0.7978845608028654f * (x + 0.044715f * x3));
    return 0.5f * x * (1.0f + t);
}
__device__ __forceinline__ uint32_t pack2h(float x, float y) {
    __half2 h = __floats2half2_rn(x, y);
    return *reinterpret_cast<uint32_t*>(&h);
}

#define LDSM_X4(r0, r1, r2, r3, addr) \
    asm volatile("ldmatrix.sync.aligned.m8n8.x4.shared.b16 {%0,%1,%2,%3}, [%4];" \
                 : "=r"(r0), "=r"(r1), "=r"(r2), "=r"(r3) : "r"(addr))

#define LDSM_X4_T(r0, r1, r2, r3, addr) \
    asm volatile("ldmatrix.sync.aligned.m8n8.x4.trans.shared.b16 {%0,%1,%2,%3}, [%4];" \
                 : "=r"(r0), "=r"(r1), "=r"(r2), "=r"(r3) : "r"(addr))

#define MMA_F16(d, a, b0v, b1v) \
    asm volatile("mma.sync.aligned.m16n8k16.row.col.f32.f16.f16.f32 " \
                 "{%0,%1,%2,%3}, {%4,%5,%6,%7}, {%8,%9}, {%0,%1,%2,%3};" \
                 : "+f"((d)[0]), "+f"((d)[1]), "+f"((d)[2]), "+f"((d)[3]) \
                 : "r"((a)[0]), "r"((a)[1]), "r"((a)[2]), "r"((a)[3]), \
                   "r"(b0v), "r"(b1v))

// ---------------- weight conversion ----------------
__global__ void wconv_kernel(const float* __restrict__ w, __half* __restrict__ o, int n4)
{
    int i = blockIdx.x * 256 + threadIdx.x;
    if (i >= n4) return;
    float4 v = ((const float4*)w)[i];
    ((uint2*)o)[i] = make_uint2(pack2h(v.x, v.y), pack2h(v.z, v.w));
}

__global__ void wconv_qkv(const float* __restrict__ Wq, const float* __restrict__ Wk,
                          const float* __restrict__ Wv, __half* __restrict__ o)
{
    int i = blockIdx.x * 256 + threadIdx.x;
    if (i >= NLAYERS * 512 * (QKVS / 4)) return;
    int c4 = i % (QKVS / 4);
    int rem = i / (QKVS / 4);
    int k = rem % 512, L = rem / 512;
    int c = c4 * 4;
    const float* src;
    if (c < 512)        src = Wq + ((size_t)L * 512 + k) * 512 + c;
    else if (c < 1024)  src = Wk + ((size_t)L * 512 + k) * 512 + (c - 512);
    else                src = Wv + ((size_t)L * 512 + k) * 512 + (c - 1024);
    float4 v = *(const float4*)src;
    ((uint2*)o)[i] = make_uint2(pack2h(v.x, v.y), pack2h(v.z, v.w));
}

__global__ void packbias_kernel(const float* __restrict__ bq, const float* __restrict__ bk,
                                const float* __restrict__ bv, float* __restrict__ out)
{
    int i = blockIdx.x * 256 + threadIdx.x;
    if (i >= NLAYERS * QKVS) return;
    int L = i / QKVS, c = i % QKVS;
    float v = (c < 512) ? bq[L * 512 + c]
            : (c < 1024) ? bk[L * 512 + c - 512]
                         : bv[L * 512 + c - 1024];
    out[i] = v;
}

// ---------------- embedding ----------------
__global__ void embed_kernel(const float* __restrict__ x_enc,
                             const float* __restrict__ Wemb,
                             float* __restrict__ h, __half* __restrict__ hh)
{
    int tok = blockIdx.x;
    int r   = blockIdx.y;
    int tid = threadIdx.x;
    int b  = r >> 5;
    int cc = r & 31;

    int kstr, j;
    if (tok < 16)       { kstr = 8; j = tok; }
    else if (tok < 48)  { kstr = 4; j = tok - 16; }
    else if (tok < 112) { kstr = 2; j = tok - 48; }
    else                { kstr = 1; j = tok - 112; }

    __shared__ float xv[PATCH_N];
    if (tid < PATCH_N) {
        int tt = kstr * (j * PATCH_N + tid);
        xv[tid] = x_enc[((size_t)b * TLEN + tt) * CCH + cc];
    }
    __syncthreads();

    float pepos = (float)(j * kstr);
    const float cln = 9.210340371976184f / (float)DM;

    for (int d = tid; d < DM; d += 256) {
        float acc = 0.0f;
        #pragma unroll
        for (int p = 0; p < PATCH_N; p++)
            acc += xv[p] * Wemb[p * DM + d];
        int i2 = d & ~1;
        float ang = pepos * __expf(-(float)i2 * cln);
        float pv = (d & 1) ? cosf(ang) : sinf(ang);
        float val = acc + pv;
        size_t gi = ((size_t)r * LTOT + tok) * DM + d;
        h[gi] = val;
        hh[gi] = __float2half_rn(val);
    }
}

// ---------------- fp16 mma.sync GEMM, 4 warps 64x64, K-slab 32, 4-stage ----------------
#define AST 40
#define BST 136
#define ST_A 0
#define ST_B 10240
#define STAGEB 18944
#define NSTG 4
#define GSMEM (NSTG * STAGEB)

__global__ __launch_bounds__(128, 2)
void gemm_mma(const __half* __restrict__ A, const __half* __restrict__ Bm,
              const float* __restrict__ bias,
              float* __restrict__ C, __half* __restrict__ Ch,
              int M, int N, int K, int doGelu)
{
    extern __shared__ char dsm[];
    uint32_t dynb = smem_u32(dsm);

    int tid  = threadIdx.x;
    int wid  = tid >> 5;
    int lane = tid & 31;
    int wm = wid & 1;
    int wn = wid >> 1;
    int m0 = blockIdx.y * 128;
    int n0 = blockIdx.x * 128;

    float acc[4][8][4];
    #pragma unroll
    for (int i = 0; i < 4; i++)
        #pragma unroll
        for (int j = 0; j < 8; j++)
            #pragma unroll
            for (int c = 0; c < 4; c++) acc[i][j][c] = 0.0f;

    uint32_t aoffL = ((uint32_t)((wm * 64 + (lane & 15)) * AST + (lane >> 4) * 8)) * 2;
    uint32_t boffL = ((uint32_t)(((lane & 7) + ((lane >> 3) & 1) * 8) * BST
                                 + wn * 64 + (lane >> 4) * 8)) * 2;

    int nslab = K >> 5;

    auto issue = [&](int j) {
        uint32_t sb = dynb + (uint32_t)(j % NSTG) * STAGEB;
        int k0 = j * 32;
        #pragma unroll
        for (int i = 0; i < 4; i++) {
            int chunk = i * 128 + tid;
            int row = chunk >> 2, c8 = (chunk & 3) * 8;
            uint32_t off = (uint32_t)(row * AST + c8) * 2;
            cpasync16(sb + ST_A + off, A + (size_t)(m0 + row) * K + k0 + c8);
        }
        #pragma unroll
        for (int i = 0; i < 4; i++) {
            int chunk = i * 128 + tid;
            int row = chunk >> 4, c8 = (chunk & 15) * 8;
            uint32_t off = (uint32_t)(row * BST + c8) * 2;
            cpasync16(sb + ST_B + off, Bm + (size_t)(k0 + row) * N + n0 + c8);
        }
        asm volatile("cp.async.commit_group;" ::: "memory");
    };

    issue(0); issue(1); issue(2);
    for (int j = 0; j < nslab; j++) {
        if (j < nslab - 2)
            asm volatile("cp.async.wait_group 2;" ::: "memory");
        else if (j == nslab - 2)
            asm volatile("cp.async.wait_group 1;" ::: "memory");
        else
            asm volatile("cp.async.wait_group 0;" ::: "memory");
        __syncthreads();

        uint32_t sb = dynb + (uint32_t)(j % NSTG) * STAGEB;
        uint32_t aB = sb + ST_A, bB = sb + ST_B;

        if (j + 3 < nslab) issue(j + 3);

        #pragma unroll
        for (int ks = 0; ks < 2; ks++) {
            uint32_t kbA = (uint32_t)(ks * 16) * 2;
            uint32_t kbB = (uint32_t)(ks * 16 * BST) * 2;

            uint32_t ah[4][4];
            #pragma unroll
            for (int mf = 0; mf < 4; mf++) {
                uint32_t off = aoffL + (uint32_t)(mf * 16 * AST) * 2 + kbA;
                LDSM_X4(ah[mf][0], ah[mf][1], ah[mf][2], ah[mf][3], aB + off);
            }
            uint32_t bh[16];
            #pragma unroll
            for (int nb = 0; nb < 4; nb++) {
                uint32_t off = boffL + (uint32_t)(nb * 16) * 2 + kbB;
                LDSM_X4_T(bh[nb * 4 + 0], bh[nb * 4 + 1], bh[nb * 4 + 2], bh[nb * 4 + 3], bB + off);
            }

            #pragma unroll
            for (int mf = 0; mf < 4; mf++)
                #pragma unroll
                for (int nf = 0; nf < 8; nf++)
                    MMA_F16(acc[mf][nf], ah[mf], bh[nf * 2], bh[nf * 2 + 1]);
        }
    }

    int rbase = m0 + wm * 64 + (lane >> 2);
    int cbase = n0 + wn * 64 + (lane & 3) * 2;
    #pragma unroll
    for (int mf = 0; mf < 4; mf++) {
        #pragma unroll
        for (int nf = 0; nf < 8; nf++) {
            int col = cbase + nf * 8;
            float b0v = bias[col], b1v = bias[col + 1];
            float v0 = acc[mf][nf][0] + b0v;
            float v1 = acc[mf][nf][1] + b1v;
            float v2 = acc[mf][nf][2] + b0v;
            float v3 = acc[mf][nf][3] + b1v;
            if (doGelu) {
                v0 = gelu_tanh(v0); v1 = gelu_tanh(v1);
                v2 = gelu_tanh(v2); v3 = gelu_tanh(v3);
            }
            int r0 = rbase + mf * 16;
            if (C) {
                *(float2*)(C + (size_t)r0 * N + col)       = make_float2(v0, v1);
                *(float2*)(C + (size_t)(r0 + 8) * N + col) = make_float2(v2, v3);
            }
            if (Ch) {
                *(uint32_t*)(Ch + (size_t)r0 * N + col)       = pack2h(v0, v1);
                *(uint32_t*)(Ch + (size_t)(r0 + 8) * N + col) = pack2h(v2, v3);
            }
        }
    }
}

// ---------------- tensor-core attention for len 64 / 128 ----------------
template<int LEN>
__global__ __launch_bounds__(256)
void attn_mma(const __half* __restrict__ qkv, __half* __restrict__ th, int start)
{
    constexpr int QST = 72;
    constexpr int KST = LEN + 8;
    constexpr int SST = LEN + 4;
    constexpr int PST = LEN + 8;

    extern __shared__ char smraw[];
    __half* sQ  = (__half*)smraw;
    __half* sKt = sQ + LEN * QST;
    float*  sS  = (float*)(sKt + 64 * KST);
    __half* sP  = (__half*)(sS + LEN * SST);

    int bid = blockIdx.x;
    int hh = bid & 7;
    int b  = bid >> 3;
    int tid = threadIdx.x;
    int wid = tid >> 5, lane = tid & 31;
    int h64 = hh * HD;
    size_t rowbase = (size_t)b * LTOT + start;

    uint32_t sQb = smem_u32(sQ), sKb = smem_u32(sKt);
    uint32_t sPb = smem_u32(sP);

    for (int e = tid; e < LEN * 16; e += 256) {
        int l = e >> 4, c4 = (e & 15) * 4;
        size_t gi = (rowbase + l) * QKVS + h64 + c4;
        uint2 qv = *(const uint2*)(qkv + gi);
        *(uint2*)(sQ + l * QST + c4) = qv;
        __half kvv[4];
        *(uint2*)kvv = *(const uint2*)(qkv + gi + 512);
        #pragma unroll
        for (int i = 0; i < 4; i++)
            sKt[(c4 + i) * KST + l] = kvv[i];
    }
    __syncthreads();

    constexpr int WMS = LEN / 32;
    constexpr int CPW = LEN / (8 / WMS);
    constexpr int NFS = CPW / 8;
    constexpr int NBS = (CPW >= 16) ? CPW / 16 : 1;
    int wm_s = wid % WMS, wn_s = wid / WMS;

    float accs[2][NFS][4];
    #pragma unroll
    for (int i = 0; i < 2; i++)
        #pragma unroll
        for (int j = 0; j < NFS; j++)
            #pragma unroll
            for (int c = 0; c < 4; c++) accs[i][j][c] = 0.0f;

    uint32_t qoff = ((uint32_t)((wm_s * 32 + (lane & 15)) * QST + (lane >> 4) * 8)) * 2;
    uint32_t koff = ((uint32_t)(((lane & 7) + ((lane >> 3) & 1) * 8) * KST
                                + wn_s * CPW + (lane >> 4) * 8)) * 2;

    #pragma unroll
    for (int ks = 0; ks < 4; ks++) {
        uint32_t aq[2][4];
        #pragma unroll
        for (int mf = 0; mf < 2; mf++) {
            uint32_t off = qoff + (uint32_t)(mf * 16 * QST + ks * 16) * 2;
            LDSM_X4(aq[mf][0], aq[mf][1], aq[mf][2], aq[mf][3], sQb + off);
        }
        uint32_t bk[NFS * 2];
        #pragma unroll
        for (int nb = 0; nb < NBS; nb++) {
            uint32_t off = koff + (uint32_t)(ks * 16 * KST + nb * 16) * 2;
            LDSM_X4_T(bk[nb * 4 + 0], bk[nb * 4 + 1], bk[nb * 4 + 2], bk[nb * 4 + 3], sKb + off);
        }
        #pragma unroll
        for (int mf = 0; mf < 2; mf++)
            #pragma unroll
            for (int nf = 0; nf < NFS; nf++)
                MMA_F16(accs[mf][nf], aq[mf], bk[nf * 2], bk[nf * 2 + 1]);
    }

    {
        int r = wm_s * 32 + (lane >> 2);
        int c0 = wn_s * CPW + (lane & 3) * 2;
        #pragma unroll
        for (int mf = 0; mf < 2; mf++)
            #pragma unroll
            for (int nf = 0; nf < NFS; nf++) {
                int rr = r + mf * 16, cc = c0 + nf * 8;
                *(float2*)&sS[rr * SST + cc] =
                    make_float2(accs[mf][nf][0] * 0.125f, accs[mf][nf][1] * 0.125f);
                *(float2*)&sS[(rr + 8) * SST + cc] =
                    make_float2(accs[mf][nf][2] * 0.125f, accs[mf][nf][3] * 0.125f);
            }
    }
    __syncthreads();

    for (int e = tid; e < LEN * 16; e += 256) {
        int l = e >> 4, c4 = (e & 15) * 4;
        uint2 vv = *(const uint2*)(qkv + (rowbase + l) * QKVS + h64 + c4 + 1024);
        *(uint2*)(sQ + l * QST + c4) = vv;
    }
    for (int r = tid; r < LEN; r += 256) {
        float* row = sS + r * SST;
        float mx = -1e30f;
        for (int m = 0; m < LEN; m++) mx = fmaxf(mx, row[m]);
        float sum = 0.0f;
        for (int m = 0; m < LEN; m++) {
            float ev = expf(row[m] - mx);
            row[m] = ev;
            sum += ev;
        }
        float inv = 1.0f / sum;
        __half* prow = sP + r * PST;
        for (int m = 0; m < LEN; m++)
            prow[m] = __float2half_rn(row[m] * inv);
    }
    __syncthreads();

    constexpr int WMP = LEN / 32;
    constexpr int DPW = 8 * WMP;
    constexpr int NFP = DPW / 8;
    constexpr int NBP = (DPW >= 16) ? DPW / 16 : 1;
    constexpr int KSP = LEN / 16;
    int wm_p = wid % WMP, wn_p = wid / WMP;

    float accp[2][NFP][4];
    #pragma unroll
    for (int i = 0; i < 2; i++)
        #pragma unroll
        for (int j = 0; j < NFP; j++)
            #pragma unroll
            for (int c = 0; c < 4; c++) accp[i][j][c] = 0.0f;

    uint32_t poff = ((uint32_t)((wm_p * 32 + (lane & 15)) * PST + (lane >> 4) * 8)) * 2;
    uint32_t voff = ((uint32_t)(((lane & 7) + ((lane >> 3) & 1) * 8) * QST
                                + wn_p * DPW + (lane >> 4) * 8)) * 2;

    #pragma unroll
    for (int ks = 0; ks < KSP; ks++) {
        uint32_t ap[2][4];
        #pragma unroll
        for (int mf = 0; mf < 2; mf++) {
            uint32_t off = poff + (uint32_t)(mf * 16 * PST + ks * 16) * 2;
            LDSM_X4(ap[mf][0], ap[mf][1], ap[mf][2], ap[mf][3], sPb + off);
        }
        uint32_t bv[NFP * 2];
        #pragma unroll
        for (int nb = 0; nb < NBP; nb++) {
            uint32_t off = voff + (uint32_t)(ks * 16 * QST + nb * 16) * 2;
            LDSM_X4_T(bv[nb * 4 + 0], bv[nb * 4 + 1], bv[nb * 4 + 2], bv[nb * 4 + 3], sQb + off);
        }
        #pragma unroll
        for (int mf = 0; mf < 2; mf++)
            #pragma unroll
            for (int nf = 0; nf < NFP; nf++)
                MMA_F16(accp[mf][nf], ap[mf], bv[nf * 2], bv[nf * 2 + 1]);
    }

    {
        int r = wm_p * 32 + (lane >> 2);
        int c0 = wn_p * DPW + (lane & 3) * 2;
        #pragma unroll
        for (int mf = 0; mf < 2; mf++)
            #pragma unroll
            for (int nf = 0; nf < NFP; nf++) {
                int rr = r + mf * 16, cc = c0 + nf * 8;
                *(uint32_t*)(th + (rowbase + rr) * DM + h64 + cc) =
                    pack2h(accp[mf][nf][0], accp[mf][nf][1]);
                *(uint32_t*)(th + (rowbase + rr + 8) * DM + h64 + cc) =
                    pack2h(accp[mf][nf][2], accp[mf][nf][3]);
            }
    }
}

// ---------------- FFMA attention for len 16 + 32 in ONE launch ----------------
// blockIdx.y: 0 -> start 0 len 16 ; 1 -> start 16 len 32
__global__ void attn_small(const __half* __restrict__ qkv,
                           __half* __restrict__ th)
{
    extern __shared__ float sm[];
    int start = (blockIdx.y == 0) ? 0 : 16;
    int len   = (blockIdx.y == 0) ? 16 : 32;
    int bid = blockIdx.x;
    int hh = bid & 7;
    int b  = bid >> 3;
    int tid = threadIdx.x;        // 256
    int h64 = hh * HD;
    size_t rowbase = (size_t)b * LTOT + start;
    int lenp = len + 4;

    float* sQ  = sm;
    float* sKt = sm + len * HD;
    float* sS  = sKt + HD * lenp;

    for (int e = tid; e < len * HD; e += 256) {
        int l = e >> 6, kk = e & 63;
        size_t gi = (rowbase + l) * QKVS + h64 + kk;
        sQ[e] = __half2float(qkv[gi]);
        sKt[kk * lenp + l] = __half2float(qkv[gi + 512]);
    }
    __syncthreads();

    int nq4 = len >> 2;
    for (int e = tid; e < len * nq4; e += 256) {
        int l  = e / nq4;
        int m4 = (e - l * nq4) * 4;
        const float* qr = sQ + l * HD;
        float ax = 0.0f, ay = 0.0f, az = 0.0f, aw = 0.0f;
        #pragma unroll 8
        for (int kk = 0; kk < HD; kk++) {
            float qv = qr[kk];
            float4 kv = *(const float4*)&sKt[kk * lenp + m4];
            ax += qv * kv.x; ay += qv * kv.y;
            az += qv * kv.z; aw += qv * kv.w;
        }
        float4 rr; rr.x = ax * 0.125f; rr.y = ay * 0.125f;
        rr.z = az * 0.125f; rr.w = aw * 0.125f;
        *(float4*)&sS[l * lenp + m4] = rr;
    }
    __syncthreads();

    for (int e = tid; e < len * HD; e += 256) {
        int l = e >> 6, kk = e & 63;
        sQ[e] = __half2float(qkv[(rowbase + l) * QKVS + h64 + kk + 1024]);
    }
    if (tid < len) {
        float* row = sS + tid * lenp;
        float mx = -1e30f;
        for (int m = 0; m < len; m++) mx = fmaxf(mx, row[m]);
        float sum = 0.0f;
        for (int m = 0; m < len; m++) {
            float ev = expf(row[m] - mx);
            row[m] = ev;
            sum += ev;
        }
        float inv = 1.0f / sum;
        for (int m = 0; m < len; m++) row[m] *= inv;
    }
    __syncthreads();

    for (int e = tid; e < len * (HD / 4); e += 256) {
        int l  = e >> 4;
        int d4 = (e & 15) * 4;
        const float* srow = sS + l * lenp;
        float ax = 0.0f, ay = 0.0f, az = 0.0f, aw = 0.0f;
        #pragma unroll 8
        for (int m = 0; m < len; m++) {
            float s = srow[m];
            float4 vv = *(const float4*)&sQ[m * HD + d4];
            ax += s * vv.x; ay += s * vv.y;
            az += s * vv.z; aw += s * vv.w;
        }
        size_t go = (rowbase + l) * DM + h64 + d4;
        *(uint2*)(th + go) = make_uint2(pack2h(ax, ay), pack2h(az, aw));
    }
}

// ---------------- residual(fp16) + LayerNorm (+ optional fp16 output) ----------------
__global__ void ln_kernel(const float* __restrict__ x, const __half* __restrict__ res,
                          const float* __restrict__ g, const float* __restrict__ bb,
                          float* __restrict__ out, __half* __restrict__ oh,
                          int hasRes)
{
    int row = blockIdx.x;
    int tid = threadIdx.x;   // 128
    float4 vv = ((const float4*)(x + (size_t)row * DM))[tid];
    if (hasRes) {
        uint2 rr = ((const uint2*)(res + (size_t)row * DM))[tid];
        __half2 r0 = *reinterpret_cast<__half2*>(&rr.x);
        __half2 r1 = *reinterpret_cast<__half2*>(&rr.y);
        vv.x += __low2float(r0);  vv.y += __high2float(r0);
        vv.z += __low2float(r1);  vv.w += __high2float(r1);
    }
    float sum = vv.x + vv.y + vv.z + vv.w;
    float sq  = vv.x * vv.x + vv.y * vv.y + vv.z * vv.z + vv.w * vv.w;

    #pragma unroll
    for (int off = 16; off; off >>= 1) {
        sum += __shfl_xor_sync(0xFFFFFFFFu, sum, off);
        sq  += __shfl_xor_sync(0xFFFFFFFFu, sq,  off);
    }
    __shared__ float red[2][4];
    int w = tid >> 5;
    if ((tid & 31) == 0) { red[0][w] = sum; red[1][w] = sq; }
    __syncthreads();
    sum = red[0][0] + red[0][1] + red[0][2] + red[0][3];
    sq  = red[1][0] + red[1][1] + red[1][2] + red[1][3];

    float mean = sum * (1.0f / DM);
    float var  = sq * (1.0f / DM) - mean * mean;
    float rstd = rsqrtf(var + 1e-5f);

    float4 gv = ((const float4*)g)[tid];
    float4 bv = ((const float4*)bb)[tid];
    float4 ov;
    ov.x = (vv.x - mean) * rstd * gv.x + bv.x;
    ov.y = (vv.y - mean) * rstd * gv.y + bv.y;
    ov.z = (vv.z - mean) * rstd * gv.z + bv.z;
    ov.w = (vv.w - mean) * rstd * gv.w + bv.w;
    ((float4*)(out + (size_t)row * DM))[tid] = ov;

    if (oh) {
        ((uint2*)(oh + (size_t)row * DM))[tid] =
            make_uint2(pack2h(ov.x, ov.y), pack2h(ov.z, ov.w));
    }
}

// ---------------- host launcher ----------------
extern "C" void kernel_launch(void* const* d_in, const int* in_sizes, int n_in,
                              void* d_out, int out_size)
{
    (void)in_sizes; (void)n_in; (void)out_size;
    const float* x_enc = (const float*)d_in[0];
    const float* W_emb = (const float*)d_in[1];
    const float* Wq    = (const float*)d_in[2];
    const float* bq    = (const float*)d_in[3];
    const float* Wk    = (const float*)d_in[4];
    const float* bk    = (const float*)d_in[5];
    const float* Wv    = (const float*)d_in[6];
    const float* bv    = (const float*)d_in[7];
    const float* Wo    = (const float*)d_in[8];
    const float* bo    = (const float*)d_in[9];
    const float* ln1_g = (const float*)d_in[10];
    const float* ln1_b = (const float*)d_in[11];
    const float* W1    = (const float*)d_in[12];
    const float* b1    = (const float*)d_in[13];
    const float* W2    = (const float*)d_in[14];
    const float* b2    = (const float*)d_in[15];
    const float* ln2_g = (const float*)d_in[16];
    const float* ln2_b = (const float*)d_in[17];
    const float* lnf_g = (const float*)d_in[18];
    const float* lnf_b = (const float*)d_in[19];

    float *h, *bqkv;
    __half *oh, *qkvh, *hh, *th, *fh, *wh;
    cudaGetSymbolAddress((void**)&h,    g_h);
    cudaGetSymbolAddress((void**)&bqkv, g_bqkv);
    cudaGetSymbolAddress((void**)&oh,   g_oh);
    cudaGetSymbolAddress((void**)&qkvh, g_qkvh);
    cudaGetSymbolAddress((void**)&hh,   g_hh);
    cudaGetSymbolAddress((void**)&th,   g_th);
    cudaGetSymbolAddress((void**)&fh,   g_fh);
    cudaGetSymbolAddress((void**)&wh,   g_wh);

    cudaFuncSetAttribute(gemm_mma, cudaFuncAttributeMaxDynamicSharedMemorySize, GSMEM);
    cudaFuncSetAttribute(attn_mma<128>, cudaFuncAttributeMaxDynamicSharedMemorySize, 138240);
    cudaFuncSetAttribute(attn_mma<64>,  cudaFuncAttributeMaxDynamicSharedMemorySize, 45056);

    const size_t WD = (size_t)DM * DM;
    const size_t WF = (size_t)DM * DFF;
    const size_t WQKV = (size_t)NLAYERS * 512 * QKVS;
    const size_t OO = WQKV, O1 = OO + 3 * WD, O2 = O1 + 3 * WF;

    wconv_qkv<<<(int)(WQKV / 4 + 255) / 256, 256>>>(Wq, Wk, Wv, wh);
    packbias_kernel<<<(NLAYERS * QKVS + 255) / 256, 256>>>(bq, bk, bv, bqkv);
    wconv_kernel<<<(int)(3 * WD / 4 + 255) / 256, 256>>>(Wo, wh + OO, (int)(3 * WD / 4));
    wconv_kernel<<<(int)(3 * WF / 4 + 255) / 256, 256>>>(W1, wh + O1, (int)(3 * WF / 4));
    wconv_kernel<<<(int)(3 * WF / 4 + 255) / 256, 256>>>(W2, wh + O2, (int)(3 * WF / 4));

    embed_kernel<<<dim3(LTOT, BSEQ), 256>>>(x_enc, W_emb, h, hh);

    dim3 gQKV(QKVS / 128, MROWS / 128);
    dim3 gD(DM / 128, MROWS / 128);
    dim3 gF(DFF / 128, MROWS / 128);

    // smem for merged small-attn launch: sized for len=32
    size_t smSmall = (size_t)(32 * HD + HD * 36 + 32 * 36) * sizeof(float);

    for (int i = 0; i < NLAYERS; i++) {
        gemm_mma<<<gQKV, 128, GSMEM>>>(hh, wh + (size_t)i * 512 * QKVS,
                                       bqkv + i * QKVS, nullptr, qkvh,
                                       MROWS, QKVS, DM, 0);

        attn_small<<<dim3(BSEQ * NHEADS, 2), 256, smSmall>>>(qkvh, th);
        attn_mma<64><<<BSEQ * NHEADS, 256, 45056>>>(qkvh, th, 48);
        attn_mma<128><<<BSEQ * NHEADS, 256, 138240>>>(qkvh, th, 112);

        gemm_mma<<<gD, 128, GSMEM>>>(th, wh + OO + i * WD,
                                     bo + i * DM, nullptr, oh, MROWS, DM, DM, 0);
        ln_kernel<<<MROWS, 128>>>(h, oh, ln1_g + i * DM, ln1_b + i * DM, h, hh, 1);

        gemm_mma<<<gF, 128, GSMEM>>>(hh, wh + O1 + i * WF,
                                     b1 + i * DFF, nullptr, fh, MROWS, DFF, DM, 1);
        gemm_mma<<<gD, 128, GSMEM>>>(fh, wh + O2 + i * WF,
                                     b2 + i * DM, nullptr, oh, MROWS, DM, DFF, 0);
        ln_kernel<<<MROWS, 128>>>(h, oh, ln2_g + i * DM, ln2_b + i * DM, h, hh, 1);
    }

    ln_kernel<<<MROWS, 128>>>(h, nullptr, lnf_g, lnf_b, (float*)d_out, nullptr, 0);
}